// round 4
// baseline (speedup 1.0000x reference)
#include <cuda_runtime.h>
#include <cuda_bf16.h>

#define NN 100000
#define NE 1600000
#define BN_EPS 1e-5f
#define SCAN_BLK 1024
#define N_SCAN_BLKS ((NN + SCAN_BLK - 1) / SCAN_BLK)   // 98
#define FULL 0xffffffffu

// ---------------- scratch (static device memory, no allocs) ----------------
__device__ float g_bufA[NN * 32];
__device__ float g_bufB[NN * 32];
__device__ float g_stats[5 * 64];
__device__ float g_ab[64];
__device__ float4 g_pool[64 * 8];
// CSR build
__device__ int g_cnt[NN];
__device__ int g_excl[NN];
__device__ int g_bsum[128];
__device__ int g_boff[128];
__device__ int g_rs[NN + 1];
__device__ int g_cur[NN];
__device__ int g_col[NE];

__device__ __forceinline__ void red_add_f32x4(float4* addr, float4 v) {
    asm volatile("red.global.add.v4.f32 [%0], {%1, %2, %3, %4};"
                 :: "l"(addr), "f"(v.x), "f"(v.y), "f"(v.z), "f"(v.w)
                 : "memory");
}

// ---------------- zero (per replay) -----------------------------------------
__global__ void zero_kernel() {
    int i = blockIdx.x * blockDim.x + threadIdx.x;
    if (i < NN) g_cnt[i] = 0;
    if (i < 5 * 64) g_stats[i] = 0.f;
    if (i < 64 * 8) g_pool[i] = make_float4(0.f, 0.f, 0.f, 0.f);
}

// ---------------- CSR build -------------------------------------------------
__global__ void count_kernel(const int* __restrict__ dsts) {
    int e = blockIdx.x * blockDim.x + threadIdx.x;
    if (e < NE) atomicAdd(&g_cnt[dsts[e]], 1);
}

__global__ void scan_a_kernel() {
    __shared__ int wsum[8];
    int base = blockIdx.x * SCAN_BLK + threadIdx.x * 4;
    int v0 = (base + 0 < NN) ? g_cnt[base + 0] : 0;
    int v1 = (base + 1 < NN) ? g_cnt[base + 1] : 0;
    int v2 = (base + 2 < NN) ? g_cnt[base + 2] : 0;
    int v3 = (base + 3 < NN) ? g_cnt[base + 3] : 0;
    int tsum = v0 + v1 + v2 + v3;
    int lane = threadIdx.x & 31, wid = threadIdx.x >> 5;
    int incl = tsum;
    #pragma unroll
    for (int off = 1; off < 32; off <<= 1) {
        int n = __shfl_up_sync(FULL, incl, off);
        if (lane >= off) incl += n;
    }
    if (lane == 31) wsum[wid] = incl;
    __syncthreads();
    if (wid == 0 && lane < 8) {
        int w = wsum[lane];
        #pragma unroll
        for (int off = 1; off < 8; off <<= 1) {
            int n = __shfl_up_sync(0xffu, w, off);
            if (lane >= off) w += n;
        }
        wsum[lane] = w;
    }
    __syncthreads();
    int off = (wid > 0 ? wsum[wid - 1] : 0) + incl - tsum;
    if (base + 0 < NN) g_excl[base + 0] = off;
    if (base + 1 < NN) g_excl[base + 1] = off + v0;
    if (base + 2 < NN) g_excl[base + 2] = off + v0 + v1;
    if (base + 3 < NN) g_excl[base + 3] = off + v0 + v1 + v2;
    if (threadIdx.x == 0) g_bsum[blockIdx.x] = wsum[7];
}

__global__ void scan_b_kernel() {
    __shared__ int s[128];
    int t = threadIdx.x;
    int orig = (t < N_SCAN_BLKS) ? g_bsum[t] : 0;
    s[t] = orig;
    __syncthreads();
    #pragma unroll
    for (int off = 1; off < 128; off <<= 1) {
        int v = (t >= off) ? s[t - off] : 0;
        __syncthreads();
        s[t] += v;
        __syncthreads();
    }
    if (t < N_SCAN_BLKS) g_boff[t] = s[t] - orig;
}

__global__ void scan_c_kernel() {
    int i = blockIdx.x * blockDim.x + threadIdx.x;
    if (i < NN) {
        int rs = g_excl[i] + g_boff[i / SCAN_BLK];
        g_rs[i] = rs;
        g_cur[i] = rs;
    }
    if (i == 0) g_rs[NN] = NE;
}

__global__ void fill_kernel(const int* __restrict__ srcs,
                            const int* __restrict__ dsts) {
    int e = blockIdx.x * blockDim.x + threadIdx.x;
    if (e >= NE) return;
    int d = dsts[e];
    int pos = atomicAdd(&g_cur[d], 1);
    g_col[pos] = srcs[e];
}

// ---------------- fused layer 1: x(F=64) -> gather -> MLP -> h -> stats -----
// one warp per node; lane L holds input features (2L, 2L+1) as float2.
__global__ __launch_bounds__(256) void fused_layer1(
    const float2* __restrict__ x2,
    const float* __restrict__ Wa, const float* __restrict__ Ba,
    const float* __restrict__ Wb, const float* __restrict__ Bb) {
    __shared__ float sWa[64 * 32];
    __shared__ float sWb[32 * 32];
    __shared__ float sB[64];
    __shared__ float sstat[64];
    int tid = threadIdx.x;
    for (int i = tid; i < 64 * 32; i += 256) sWa[i] = Wa[i];
    for (int i = tid; i < 1024;    i += 256) sWb[i] = Wb[i];
    if (tid < 32) sB[tid] = Ba[tid];
    else if (tid < 64) sB[tid] = Bb[tid - 32];
    if (tid < 64) sstat[tid] = 0.f;
    __syncthreads();

    int lane = tid & 31, wid = tid >> 5;
    int nwarp = gridDim.x * 8;
    float ssum = 0.f, ssq = 0.f;

    for (int node = blockIdx.x * 8 + wid; node < NN; node += nwarp) {
        int e0 = g_rs[node], e1 = g_rs[node + 1];
        float2 self = x2[(size_t)node * 32 + lane];
        float a0x = self.x, a0y = self.y, a1x = 0.f, a1y = 0.f;
        int e = e0;
        while (e < e1) {
            int n = e1 - e; if (n > 32) n = 32;
            int idx = (e + lane < e1) ? __ldg(&g_col[e + lane]) : 0;
            int k = 0;
            for (; k + 4 <= n; k += 4) {
                int s0 = __shfl_sync(FULL, idx, k);
                int s1 = __shfl_sync(FULL, idx, k + 1);
                int s2 = __shfl_sync(FULL, idx, k + 2);
                int s3 = __shfl_sync(FULL, idx, k + 3);
                float2 v0 = x2[(size_t)s0 * 32 + lane];
                float2 v1 = x2[(size_t)s1 * 32 + lane];
                float2 v2 = x2[(size_t)s2 * 32 + lane];
                float2 v3 = x2[(size_t)s3 * 32 + lane];
                a0x += v0.x + v2.x; a0y += v0.y + v2.y;
                a1x += v1.x + v3.x; a1y += v1.y + v3.y;
            }
            for (; k < n; k++) {
                int s = __shfl_sync(FULL, idx, k);
                float2 v = x2[(size_t)s * 32 + lane];
                a0x += v.x; a0y += v.y;
            }
            e += n;
        }
        float aggx = a0x + a1x, aggy = a0y + a1y;

        // GEMM1: t[k] = Ba[k] + sum_j agg[j] * Wa[j*32+k]   (j over 64)
        float t = sB[lane];
        #pragma unroll
        for (int j = 0; j < 32; j++) {
            float vx = __shfl_sync(FULL, aggx, j);
            float vy = __shfl_sync(FULL, aggy, j);
            t = fmaf(vx, sWa[(2 * j) * 32 + lane], t);
            t = fmaf(vy, sWa[(2 * j + 1) * 32 + lane], t);
        }
        t = fmaxf(t, 0.f);
        // GEMM2
        float o = sB[32 + lane];
        #pragma unroll
        for (int j = 0; j < 32; j++) {
            float tj = __shfl_sync(FULL, t, j);
            o = fmaf(tj, sWb[j * 32 + lane], o);
        }
        o = fmaxf(o, 0.f);
        g_bufA[(size_t)node * 32 + lane] = o;
        ssum += o; ssq += o * o;
    }

    atomicAdd(&sstat[lane], ssum);
    atomicAdd(&sstat[32 + lane], ssq);
    __syncthreads();
    if (tid < 64) atomicAdd(&g_stats[tid], sstat[tid]);
}

// ---------------- fused layer 2-5 (F=32, lazy BN on input) ------------------
__global__ __launch_bounds__(256) void fused_layer32(
    const float* __restrict__ Wa, const float* __restrict__ Ba,
    const float* __restrict__ Wb, const float* __restrict__ Bb,
    int layer, int flip) {
    __shared__ float sWa[1024];
    __shared__ float sWb[1024];
    __shared__ float sB[64];
    __shared__ float sstat[64];
    int tid = threadIdx.x;
    for (int i = tid; i < 1024; i += 256) { sWa[i] = Wa[i]; sWb[i] = Wb[i]; }
    if (tid < 32) sB[tid] = Ba[tid];
    else if (tid < 64) sB[tid] = Bb[tid - 32];
    if (tid < 64) sstat[tid] = 0.f;
    __syncthreads();

    int lane = tid & 31, wid = tid >> 5;
    const float* fin  = flip ? g_bufB : g_bufA;
    float*       fout = flip ? g_bufA : g_bufB;
    float a = g_ab[lane], b = g_ab[32 + lane];
    int nwarp = gridDim.x * 8;
    float ssum = 0.f, ssq = 0.f;

    for (int node = blockIdx.x * 8 + wid; node < NN; node += nwarp) {
        int e0 = g_rs[node], e1 = g_rs[node + 1];
        float acc0 = fin[(size_t)node * 32 + lane];
        float acc1 = 0.f, acc2 = 0.f, acc3 = 0.f;
        int e = e0;
        while (e < e1) {
            int n = e1 - e; if (n > 32) n = 32;
            int idx = (e + lane < e1) ? __ldg(&g_col[e + lane]) : 0;
            int k = 0;
            for (; k + 4 <= n; k += 4) {
                int s0 = __shfl_sync(FULL, idx, k);
                int s1 = __shfl_sync(FULL, idx, k + 1);
                int s2 = __shfl_sync(FULL, idx, k + 2);
                int s3 = __shfl_sync(FULL, idx, k + 3);
                float v0 = fin[(size_t)s0 * 32 + lane];
                float v1 = fin[(size_t)s1 * 32 + lane];
                float v2 = fin[(size_t)s2 * 32 + lane];
                float v3 = fin[(size_t)s3 * 32 + lane];
                acc0 += v0; acc1 += v1; acc2 += v2; acc3 += v3;
            }
            for (; k < n; k++) {
                int s = __shfl_sync(FULL, idx, k);
                acc0 += fin[(size_t)s * 32 + lane];
            }
            e += n;
        }
        float cnt = (float)(e1 - e0 + 1);
        // lazy BN: sum of (a*h+b) over (deg+1) rows = a*sum + cnt*b
        float agg = fmaf(a, (acc0 + acc1) + (acc2 + acc3), cnt * b);

        float t = sB[lane];
        #pragma unroll
        for (int j = 0; j < 32; j++) {
            float xj = __shfl_sync(FULL, agg, j);
            t = fmaf(xj, sWa[j * 32 + lane], t);
        }
        t = fmaxf(t, 0.f);
        float o = sB[32 + lane];
        #pragma unroll
        for (int j = 0; j < 32; j++) {
            float tj = __shfl_sync(FULL, t, j);
            o = fmaf(tj, sWb[j * 32 + lane], o);
        }
        o = fmaxf(o, 0.f);
        fout[(size_t)node * 32 + lane] = o;
        ssum += o; ssq += o * o;
    }

    atomicAdd(&sstat[lane], ssum);
    atomicAdd(&sstat[32 + lane], ssq);
    __syncthreads();
    if (tid < 64) atomicAdd(&g_stats[layer * 64 + tid], sstat[tid]);
}

// ---------------- BN coefficients -------------------------------------------
__global__ void finalize_kernel(int l, const float* __restrict__ bn_g,
                                const float* __restrict__ bn_b) {
    int c = threadIdx.x;
    if (c >= 32) return;
    float sum = g_stats[l * 64 + c];
    float sq  = g_stats[l * 64 + 32 + c];
    const float invN = 1.f / (float)NN;
    float mu  = sum * invN;
    float var = sq * invN - mu * mu;
    float a = bn_g[l * 32 + c] * rsqrtf(var + BN_EPS);
    g_ab[c]      = a;
    g_ab[32 + c] = bn_b[l * 32 + c] - mu * a;
}

// ---------------- global add pool (reads bufA, lazy BN) ---------------------
__global__ void pool_kernel(const int* __restrict__ batch) {
    int tid = blockIdx.x * blockDim.x + threadIdx.x;
    if (tid >= NN * 8) return;
    int n = tid >> 3, c = tid & 7;
    const float4* h4 = (const float4*)g_bufA;
    float4 v = h4[(size_t)n * 8 + c];
    int col = c * 4;
    v.x = fmaf(v.x, g_ab[col + 0], g_ab[32 + col + 0]);
    v.y = fmaf(v.y, g_ab[col + 1], g_ab[32 + col + 1]);
    v.z = fmaf(v.z, g_ab[col + 2], g_ab[32 + col + 2]);
    v.w = fmaf(v.w, g_ab[col + 3], g_ab[32 + col + 3]);
    int g = batch[n];
    red_add_f32x4(&g_pool[g * 8 + c], v);
}

// ---------------- head ------------------------------------------------------
__global__ void head_kernel(const float* __restrict__ fc1w, const float* __restrict__ fc1b,
                            const float* __restrict__ fc2w, const float* __restrict__ fc2b,
                            float* __restrict__ out) {
    int g = threadIdx.x;
    if (g >= 64) return;
    float in[32];
    #pragma unroll
    for (int j = 0; j < 8; j++) {
        float4 v = g_pool[g * 8 + j];
        in[4*j+0] = v.x; in[4*j+1] = v.y; in[4*j+2] = v.z; in[4*j+3] = v.w;
    }
    float t[32];
    #pragma unroll
    for (int k = 0; k < 32; k++) t[k] = fc1b[k];
    #pragma unroll
    for (int j = 0; j < 32; j++) {
        float xv = in[j];
        #pragma unroll
        for (int k = 0; k < 32; k++) t[k] = fmaf(xv, fc1w[j * 32 + k], t[k]);
    }
    #pragma unroll
    for (int k = 0; k < 32; k++) t[k] = fmaxf(t[k], 0.f);
    float o[10];
    #pragma unroll
    for (int c = 0; c < 10; c++) o[c] = fc2b[c];
    #pragma unroll
    for (int j = 0; j < 32; j++) {
        float xv = t[j];
        #pragma unroll
        for (int c = 0; c < 10; c++) o[c] = fmaf(xv, fc2w[j * 10 + c], o[c]);
    }
    #pragma unroll
    for (int c = 0; c < 10; c++) out[g * 10 + c] = o[c];
}

// ---------------- launch ----------------------------------------------------
extern "C" void kernel_launch(void* const* d_in, const int* in_sizes, int n_in,
                              void* d_out, int out_size) {
    const float* x     = (const float*)d_in[0];
    const int*   ei    = (const int*)d_in[1];
    const int*   batch = (const int*)d_in[2];
    const float* w1a = (const float*)d_in[3];
    const float* b1a = (const float*)d_in[4];
    const float* w1b = (const float*)d_in[5];
    const float* b1b = (const float*)d_in[6];
    const float* Wa  = (const float*)d_in[7];
    const float* Ba  = (const float*)d_in[8];
    const float* Wb  = (const float*)d_in[9];
    const float* Bb  = (const float*)d_in[10];
    const float* bng = (const float*)d_in[11];
    const float* bnb = (const float*)d_in[12];
    const float* fc1w = (const float*)d_in[13];
    const float* fc1b = (const float*)d_in[14];
    const float* fc2w = (const float*)d_in[15];
    const float* fc2b = (const float*)d_in[16];
    float* out = (float*)d_out;

    const int* srcs = ei;
    const int* dsts = ei + NE;

    // CSR build
    zero_kernel<<<(NN + 255) / 256, 256>>>();
    count_kernel<<<(NE + 255) / 256, 256>>>(dsts);
    scan_a_kernel<<<N_SCAN_BLKS, 256>>>();
    scan_b_kernel<<<1, 128>>>();
    scan_c_kernel<<<(NN + 255) / 256, 256>>>();
    fill_kernel<<<(NE + 255) / 256, 256>>>(srcs, dsts);

    const int GRID = 1184;  // 8 * 148 SMs

    // layer 1
    fused_layer1<<<GRID, 256>>>((const float2*)x, w1a, b1a, w1b, b1b);
    finalize_kernel<<<1, 32>>>(0, bng, bnb);

    // layers 2-5 (buffers: A->B->A->B->A)
    for (int l = 1; l <= 4; l++) {
        int li = l - 1;
        int flip = (l & 1);   // l=1: read A (flip? fin = B : A) -> need fin=A => flip=0
        // l=1: fin=A out=B ; l=2: fin=B out=A ; l=3: fin=A out=B ; l=4: fin=B out=A
        flip = ((l - 1) & 1); // 0,1,0,1
        fused_layer32<<<GRID, 256>>>(Wa + li * 1024, Ba + li * 32,
                                     Wb + li * 1024, Bb + li * 32, l, flip);
        finalize_kernel<<<1, 32>>>(l, bng, bnb);
    }

    // pool + head (final h in bufA after layer 5)
    pool_kernel<<<(NN * 8 + 255) / 256, 256>>>(batch);
    head_kernel<<<1, 64>>>(fc1w, fc1b, fc2w, fc2b, out);
}

// round 6
// speedup vs baseline: 1.4331x; 1.4331x over previous
#include <cuda_runtime.h>
#include <cuda_bf16.h>

#define NN 100000
#define NE 1600000
#define BN_EPS 1e-5f
#define SCAN_BLK 1024
#define N_SCAN_BLKS ((NN + SCAN_BLK - 1) / SCAN_BLK)   // 98
#define FULL 0xffffffffu
#define CNT_BLKS ((NE + 255) / 256)                     // 6250
#define PROJ_BLKS ((NN + 7) / 8)                        // 12500 (8 warps/block)

// ---------------- scratch (static device memory, no allocs) ----------------
__device__ float g_bufA[NN * 32];     // h / proj output
__device__ float g_agg[NN * 32];      // aggregated features
__device__ float g_stats[5 * 64];     // zero-init; self-cleaned by finalize
__device__ float g_ab[64];            // BN a[32], b[32] (for pool)
__device__ float g_Wap[1024];         // folded Wa' = diag(a)*Wa
__device__ float g_cvec[32];          // c = b @ Wa
__device__ float4 g_pool[64 * 8];     // zeroed by combo each replay
// CSR
__device__ int g_cnt[NN];             // zero-init; self-cleaned by scan_a
__device__ int g_excl[NN];
__device__ int g_bsum[128];
__device__ int g_boff[128];
__device__ int g_rs[NN + 1];
__device__ int g_cur[NN];
__device__ int g_col[NE];

__device__ __forceinline__ void red_add_f32x4(float4* addr, float4 v) {
    asm volatile("red.global.add.v4.f32 [%0], {%1, %2, %3, %4};"
                 :: "l"(addr), "f"(v.x), "f"(v.y), "f"(v.z), "f"(v.w)
                 : "memory");
}

// ---------------- launch 1: count + proj (p = x @ W1a) + zero pool ----------
__global__ __launch_bounds__(256) void combo_kernel(
    const float2* __restrict__ x2, const float* __restrict__ W1a,
    const int* __restrict__ dsts) {
    __shared__ float sW[2048];        // 64x32
    int tid = threadIdx.x;
    if (blockIdx.x < CNT_BLKS) {
        int e = blockIdx.x * 256 + tid;
        if (e < NE) atomicAdd(&g_cnt[dsts[e]], 1);
        if (blockIdx.x == 0) {
            float* p = (float*)g_pool;
            for (int i = tid; i < 64 * 8 * 4; i += 256) p[i] = 0.f;
        }
        return;
    }
    // proj: warp-per-node shfl GEMM (64 -> 32)
    for (int i = tid; i < 2048; i += 256) sW[i] = W1a[i];
    __syncthreads();
    int lane = tid & 31, wid = tid >> 5;
    int node = (blockIdx.x - CNT_BLKS) * 8 + wid;
    if (node >= NN) return;
    float2 xv = x2[(size_t)node * 32 + lane];
    float t = 0.f;
    #pragma unroll
    for (int j = 0; j < 32; j++) {
        float bx = __shfl_sync(FULL, xv.x, j);
        float by = __shfl_sync(FULL, xv.y, j);
        t = fmaf(bx, sW[(2 * j) * 32 + lane], t);
        t = fmaf(by, sW[(2 * j + 1) * 32 + lane], t);
    }
    g_bufA[(size_t)node * 32 + lane] = t;
}

// ---------------- CSR scan (self-cleans g_cnt) ------------------------------
__global__ void scan_a_kernel() {
    __shared__ int wsum[8];
    int base = blockIdx.x * SCAN_BLK + threadIdx.x * 4;
    int v0 = (base + 0 < NN) ? g_cnt[base + 0] : 0;
    int v1 = (base + 1 < NN) ? g_cnt[base + 1] : 0;
    int v2 = (base + 2 < NN) ? g_cnt[base + 2] : 0;
    int v3 = (base + 3 < NN) ? g_cnt[base + 3] : 0;
    if (base + 0 < NN) g_cnt[base + 0] = 0;
    if (base + 1 < NN) g_cnt[base + 1] = 0;
    if (base + 2 < NN) g_cnt[base + 2] = 0;
    if (base + 3 < NN) g_cnt[base + 3] = 0;
    int tsum = v0 + v1 + v2 + v3;
    int lane = threadIdx.x & 31, wid = threadIdx.x >> 5;
    int incl = tsum;
    #pragma unroll
    for (int off = 1; off < 32; off <<= 1) {
        int n = __shfl_up_sync(FULL, incl, off);
        if (lane >= off) incl += n;
    }
    if (lane == 31) wsum[wid] = incl;
    __syncthreads();
    if (wid == 0 && lane < 8) {
        int w = wsum[lane];
        #pragma unroll
        for (int off = 1; off < 8; off <<= 1) {
            int n = __shfl_up_sync(0xffu, w, off);
            if (lane >= off) w += n;
        }
        wsum[lane] = w;
    }
    __syncthreads();
    int off = (wid > 0 ? wsum[wid - 1] : 0) + incl - tsum;
    if (base + 0 < NN) g_excl[base + 0] = off;
    if (base + 1 < NN) g_excl[base + 1] = off + v0;
    if (base + 2 < NN) g_excl[base + 2] = off + v0 + v1;
    if (base + 3 < NN) g_excl[base + 3] = off + v0 + v1 + v2;
    if (threadIdx.x == 0) g_bsum[blockIdx.x] = wsum[7];
}

__global__ void scan_b_kernel() {
    __shared__ int s[128];
    int t = threadIdx.x;
    int orig = (t < N_SCAN_BLKS) ? g_bsum[t] : 0;
    s[t] = orig;
    __syncthreads();
    #pragma unroll
    for (int off = 1; off < 128; off <<= 1) {
        int v = (t >= off) ? s[t - off] : 0;
        __syncthreads();
        s[t] += v;
        __syncthreads();
    }
    if (t < N_SCAN_BLKS) g_boff[t] = s[t] - orig;
}

__global__ void scan_c_kernel() {
    int i = blockIdx.x * blockDim.x + threadIdx.x;
    if (i < NN) {
        int rs = g_excl[i] + g_boff[i / SCAN_BLK];
        g_rs[i] = rs;
        g_cur[i] = rs;
    }
    if (i == 0) g_rs[NN] = NE;
}

__global__ void fill_kernel(const int* __restrict__ srcs,
                            const int* __restrict__ dsts) {
    int e = blockIdx.x * blockDim.x + threadIdx.x;
    if (e >= NE) return;
    int d = dsts[e];
    int pos = atomicAdd(&g_cur[d], 1);
    g_col[pos] = srcs[e];
}

// ---------------- gather: agg[n] = h[n] + sum_{j in N(n)} h[j]  (32-dim) ----
// 8 lanes per node, lane c holds float4 channel c; 4x unrolled independent loads.
__global__ __launch_bounds__(256) void gather_kernel() {
    int tid = blockIdx.x * 256 + threadIdx.x;
    int node = tid >> 3;
    int c = tid & 7;
    if (node >= NN) return;
    const float4* fin = (const float4*)g_bufA;
    int e0 = g_rs[node], e1 = g_rs[node + 1];
    float4 a0 = fin[(size_t)node * 8 + c];
    float4 a1 = make_float4(0.f, 0.f, 0.f, 0.f);
    float4 a2 = make_float4(0.f, 0.f, 0.f, 0.f);
    float4 a3 = make_float4(0.f, 0.f, 0.f, 0.f);
    int e = e0;
    for (; e + 4 <= e1; e += 4) {
        int s0 = __ldg(&g_col[e + 0]);
        int s1 = __ldg(&g_col[e + 1]);
        int s2 = __ldg(&g_col[e + 2]);
        int s3 = __ldg(&g_col[e + 3]);
        float4 v0 = fin[(size_t)s0 * 8 + c];
        float4 v1 = fin[(size_t)s1 * 8 + c];
        float4 v2 = fin[(size_t)s2 * 8 + c];
        float4 v3 = fin[(size_t)s3 * 8 + c];
        a0.x += v0.x; a0.y += v0.y; a0.z += v0.z; a0.w += v0.w;
        a1.x += v1.x; a1.y += v1.y; a1.z += v1.z; a1.w += v1.w;
        a2.x += v2.x; a2.y += v2.y; a2.z += v2.z; a2.w += v2.w;
        a3.x += v3.x; a3.y += v3.y; a3.z += v3.z; a3.w += v3.w;
    }
    for (; e < e1; e++) {
        int s = __ldg(&g_col[e]);
        float4 v = fin[(size_t)s * 8 + c];
        a0.x += v.x; a0.y += v.y; a0.z += v.z; a0.w += v.w;
    }
    float4 r;
    r.x = (a0.x + a1.x) + (a2.x + a3.x);
    r.y = (a0.y + a1.y) + (a2.y + a3.y);
    r.z = (a0.z + a1.z) + (a2.z + a3.z);
    r.w = (a0.w + a1.w) + (a2.w + a3.w);
    ((float4*)g_agg)[(size_t)node * 8 + c] = r;
}

// ---------------- MLP (+fused stats). FIRST: skip GEMM1 (pre-projected) ----
template<bool FIRST>
__global__ __launch_bounds__(128) void mlp_kernel(
    const float* __restrict__ Wb, const float* __restrict__ Ba,
    const float* __restrict__ Bb, int layer) {
    __shared__ float sW1[1024];
    __shared__ float sW2[1024];
    __shared__ float sBa[32], sBb[32], sC[32];
    __shared__ float sx[128 * 33];
    int tid = threadIdx.x;
    for (int i = tid; i < 1024; i += 128) {
        if (!FIRST) sW1[i] = g_Wap[i];
        sW2[i] = Wb[i];
    }
    if (tid < 32) {
        sBa[tid] = Ba[tid];
        sBb[tid] = Bb[tid];
        sC[tid] = FIRST ? 0.f : g_cvec[tid];
    }
    int node0 = blockIdx.x * 128;
    // stage agg tile (coalesced)
    for (int idx = tid; idx < 128 * 8; idx += 128) {
        int row = idx >> 3, cc = idx & 7;
        if (node0 + row < NN) {
            float4 v = ((const float4*)g_agg)[(size_t)(node0 + row) * 8 + cc];
            float* d = &sx[row * 33 + cc * 4];
            d[0] = v.x; d[1] = v.y; d[2] = v.z; d[3] = v.w;
        }
    }
    __syncthreads();

    int node = node0 + tid;
    bool active = node < NN;
    float o[32];
    if (active) {
        const float* xr = &sx[tid * 33];
        float t[32];
        if (FIRST) {
            #pragma unroll
            for (int k = 0; k < 32; k++) t[k] = fmaxf(xr[k] + sBa[k], 0.f);
        } else {
            float cnt = (float)(g_rs[node + 1] - g_rs[node] + 1);
            #pragma unroll
            for (int k = 0; k < 32; k++) t[k] = fmaf(cnt, sC[k], sBa[k]);
            #pragma unroll
            for (int j = 0; j < 32; j++) {
                float xv = xr[j];
                #pragma unroll
                for (int k = 0; k < 32; k++) t[k] = fmaf(xv, sW1[j * 32 + k], t[k]);
            }
            #pragma unroll
            for (int k = 0; k < 32; k++) t[k] = fmaxf(t[k], 0.f);
        }
        #pragma unroll
        for (int k = 0; k < 32; k++) o[k] = sBb[k];
        #pragma unroll
        for (int j = 0; j < 32; j++) {
            float tj = t[j];
            #pragma unroll
            for (int k = 0; k < 32; k++) o[k] = fmaf(tj, sW2[j * 32 + k], o[k]);
        }
        #pragma unroll
        for (int k = 0; k < 32; k++) o[k] = fmaxf(o[k], 0.f);
    } else {
        #pragma unroll
        for (int k = 0; k < 32; k++) o[k] = 0.f;
    }
    __syncthreads();   // staging reads done before overwrite
    {
        float* xr = &sx[tid * 33];
        #pragma unroll
        for (int k = 0; k < 32; k++) xr[k] = o[k];
    }
    __syncthreads();
    // coalesced store h
    for (int idx = tid; idx < 128 * 8; idx += 128) {
        int row = idx >> 3, cc = idx & 7;
        if (node0 + row < NN) {
            const float* s = &sx[row * 33 + cc * 4];
            ((float4*)g_bufA)[(size_t)(node0 + row) * 8 + cc] =
                make_float4(s[0], s[1], s[2], s[3]);
        }
    }
    // fused stats: 64 threads, col sums / sumsq over 128 rows
    if (tid < 64) {
        int col = tid & 31;
        bool sq = tid >= 32;
        float s = 0.f;
        for (int r = 0; r < 128; r++) {
            float v = sx[r * 33 + col];
            s += sq ? v * v : v;
        }
        atomicAdd(&g_stats[layer * 64 + (sq ? 32 : 0) + col], s);
    }
}

// ---------------- finalize: BN coeffs (+fold into next Wa) ------------------
// RACE FIX: read stats -> syncthreads -> zero stats.
__global__ void finalize_kernel(int l, const float* __restrict__ bn_g,
                                const float* __restrict__ bn_b,
                                const float* __restrict__ WaNext, int fold) {
    __shared__ float sa[32], sb[32];
    int tid = threadIdx.x;
    if (tid < 32) {
        float sum = g_stats[l * 64 + tid];
        float sq  = g_stats[l * 64 + 32 + tid];
        const float invN = 1.f / (float)NN;
        float mu  = sum * invN;
        float var = fmaxf(sq * invN - mu * mu, 0.f);
        float a = bn_g[l * 32 + tid] * rsqrtf(var + BN_EPS);
        float b = bn_b[l * 32 + tid] - mu * a;
        g_ab[tid] = a; g_ab[32 + tid] = b;
        sa[tid] = a; sb[tid] = b;
    }
    __syncthreads();                       // reads done before zeroing
    if (tid < 64) g_stats[l * 64 + tid] = 0.f;
    if (fold) {
        int j = tid >> 5;
        g_Wap[tid] = sa[j] * WaNext[tid];
        if (tid < 32) {
            float c = 0.f;
            #pragma unroll
            for (int j2 = 0; j2 < 32; j2++)
                c = fmaf(sb[j2], WaNext[j2 * 32 + tid], c);
            g_cvec[tid] = c;
        }
    }
}

// ---------------- global add pool (lazy BN on final h) ----------------------
__global__ void pool_kernel(const int* __restrict__ batch) {
    int tid = blockIdx.x * blockDim.x + threadIdx.x;
    if (tid >= NN * 8) return;
    int n = tid >> 3, c = tid & 7;
    float4 v = ((const float4*)g_bufA)[(size_t)n * 8 + c];
    int col = c * 4;
    v.x = fmaf(v.x, g_ab[col + 0], g_ab[32 + col + 0]);
    v.y = fmaf(v.y, g_ab[col + 1], g_ab[32 + col + 1]);
    v.z = fmaf(v.z, g_ab[col + 2], g_ab[32 + col + 2]);
    v.w = fmaf(v.w, g_ab[col + 3], g_ab[32 + col + 3]);
    int g = batch[n];
    red_add_f32x4(&g_pool[g * 8 + c], v);
}

// ---------------- head ------------------------------------------------------
__global__ void head_kernel(const float* __restrict__ fc1w, const float* __restrict__ fc1b,
                            const float* __restrict__ fc2w, const float* __restrict__ fc2b,
                            float* __restrict__ out) {
    int g = threadIdx.x;
    if (g >= 64) return;
    float in[32];
    #pragma unroll
    for (int j = 0; j < 8; j++) {
        float4 v = g_pool[g * 8 + j];
        in[4*j+0] = v.x; in[4*j+1] = v.y; in[4*j+2] = v.z; in[4*j+3] = v.w;
    }
    float t[32];
    #pragma unroll
    for (int k = 0; k < 32; k++) t[k] = fc1b[k];
    #pragma unroll
    for (int j = 0; j < 32; j++) {
        float xv = in[j];
        #pragma unroll
        for (int k = 0; k < 32; k++) t[k] = fmaf(xv, fc1w[j * 32 + k], t[k]);
    }
    #pragma unroll
    for (int k = 0; k < 32; k++) t[k] = fmaxf(t[k], 0.f);
    float o[10];
    #pragma unroll
    for (int c = 0; c < 10; c++) o[c] = fc2b[c];
    #pragma unroll
    for (int j = 0; j < 32; j++) {
        float xv = t[j];
        #pragma unroll
        for (int c = 0; c < 10; c++) o[c] = fmaf(xv, fc2w[j * 10 + c], o[c]);
    }
    #pragma unroll
    for (int c = 0; c < 10; c++) out[g * 10 + c] = o[c];
}

// ---------------- launch ----------------------------------------------------
extern "C" void kernel_launch(void* const* d_in, const int* in_sizes, int n_in,
                              void* d_out, int out_size) {
    const float* x     = (const float*)d_in[0];
    const int*   ei    = (const int*)d_in[1];
    const int*   batch = (const int*)d_in[2];
    const float* w1a = (const float*)d_in[3];
    const float* b1a = (const float*)d_in[4];
    const float* w1b = (const float*)d_in[5];
    const float* b1b = (const float*)d_in[6];
    const float* Wa  = (const float*)d_in[7];
    const float* Ba  = (const float*)d_in[8];
    const float* Wb  = (const float*)d_in[9];
    const float* Bb  = (const float*)d_in[10];
    const float* bng = (const float*)d_in[11];
    const float* bnb = (const float*)d_in[12];
    const float* fc1w = (const float*)d_in[13];
    const float* fc1b = (const float*)d_in[14];
    const float* fc2w = (const float*)d_in[15];
    const float* fc2b = (const float*)d_in[16];
    float* out = (float*)d_out;

    const int* srcs = ei;
    const int* dsts = ei + NE;

    const int GATHER_GRID = (NN * 8 + 255) / 256;   // 3125
    const int MLP_GRID = (NN + 127) / 128;          // 782

    // launches 1-5: CSR build + proj
    combo_kernel<<<CNT_BLKS + PROJ_BLKS, 256>>>((const float2*)x, w1a, dsts);
    scan_a_kernel<<<N_SCAN_BLKS, 256>>>();
    scan_b_kernel<<<1, 128>>>();
    scan_c_kernel<<<(NN + 255) / 256, 256>>>();
    fill_kernel<<<(NE + 255) / 256, 256>>>(srcs, dsts);

    // layer 1 (launch 6 = gather, gets profiled)
    gather_kernel<<<GATHER_GRID, 256>>>();
    mlp_kernel<true><<<MLP_GRID, 128>>>(w1b, b1a, b1b, 0);
    finalize_kernel<<<1, 1024>>>(0, bng, bnb, Wa, 1);

    // layers 2-5
    for (int i = 0; i < 4; i++) {
        gather_kernel<<<GATHER_GRID, 256>>>();
        mlp_kernel<false><<<MLP_GRID, 128>>>(Wb + i * 1024, Ba + i * 32,
                                             Bb + i * 32, i + 1);
        int fold = (i < 3) ? 1 : 0;
        const float* WaNext = fold ? (Wa + (i + 1) * 1024) : Wa;
        finalize_kernel<<<1, 1024>>>(i + 1, bng, bnb, WaNext, fold);
    }

    pool_kernel<<<(NN * 8 + 255) / 256, 256>>>(batch);
    head_kernel<<<1, 64>>>(fc1w, fc1b, fc2w, fc2b, out);
}